// round 8
// baseline (speedup 1.0000x reference)
#include <cuda_runtime.h>
#include <cuda_bf16.h>

// TextureMartingaleModule: per-channel 3x3 GLCM features, zero padding.
// x: [8,16,256,256] f32 -> out: [8,64,256,256] f32
//   contrast    = mean(((p-mean)/std)^2),  std = sqrt(sd/8)+eps
//   energy      = mean(p^2)
//   entropy     = -mean(p*log(p+eps))
//   homogeneity = 1 / mean(1 + |p-mean|)
// M = (f + eps) * e^{-0.5}   (theta = 1)
//
// Identities (validated R4, rel_err 1.5e-7):
//   sd = S2 - S1*mean
//   contrast = (8/9)/(1 + eps*rsqrt(sd/8))^2 ~= (8/9)*(1 - 2*eps*rsqrt(sd/8))
//     -> bit-trick rsqrt (3.5% err on an O(1e-5) correction term) => no MUFU.
//
// Layout: smem holds interleaved float2 (p, p*log(p+eps)) -> 1 LDS.64 per tap.
// Thread = 2 adjacent output cols x 4 rows (rolling window down the rows).
// Block 128 thr, 9.25KB smem, launch_bounds(128,10) -> 40 warps/SM.

#define EPSF 1e-6f
#define EXPN 0.60653065971263342f   /* e^-0.5 */
#define EPSC (EPSF * EXPN)
#define SW 34                        /* smem tile: 34 rows x 34 float2 cols */

__device__ __forceinline__ float4 feat(float S1, float S2, float SL,
    float a0, float b0, float c0,
    float a1, float b1, float c1,
    float a2, float b2, float c2)
{
    const float inv9 = 1.0f / 9.0f;
    float mean = S1 * inv9;
    float sd = fmaxf(fmaf(-S1, mean, S2), 1e-12f);   // sum (p-mean)^2

    // contrast = (8/9)*(1 - 2*eps*rsqrt(sd/8)), bit-trick rsqrt (no NR, no MUFU)
    float r = __int_as_float(0x5f3759df - (__float_as_int(sd * 0.125f) >> 1));
    float contrast = fmaxf((8.0f / 9.0f) * fmaf(-2.0f * EPSF, r, 1.0f), 0.0f);

    float a = fabsf(a0 - mean);
    a += fabsf(b0 - mean); a += fabsf(c0 - mean);
    a += fabsf(a1 - mean); a += fabsf(b1 - mean); a += fabsf(c1 - mean);
    a += fabsf(a2 - mean); a += fabsf(b2 - mean); a += fabsf(c2 - mean);
    float homog = __fdividef(1.0f, fmaf(a, inv9, 1.0f));

    return make_float4(contrast, S2 * inv9, -SL * inv9, homog);
}

// Load 4 taps (float2: p, plog) of smem row s; emit p's and L/R row sums.
#define LOADROW(s, PA, PB, PC, PD, RSL, RSR, RQL, RQR, RLL, RLR)             \
    {                                                                         \
        const float2 u0 = sm[(s) * SW + j0];                                  \
        const float2 u1 = sm[(s) * SW + j0 + 1];                              \
        const float2 u2 = sm[(s) * SW + j0 + 2];                              \
        const float2 u3 = sm[(s) * SW + j0 + 3];                              \
        PA = u0.x; PB = u1.x; PC = u2.x; PD = u3.x;                           \
        float t  = PB + PC;                                                   \
        RSL = PA + t;                  RSR = t + PD;                          \
        float tq = fmaf(PB, PB, PC * PC);                                     \
        RQL = fmaf(PA, PA, tq);        RQR = fmaf(PD, PD, tq);                \
        float tl = u1.y + u2.y;                                               \
        RLL = u0.y + tl;               RLR = tl + u3.y;                       \
    }

__global__ __launch_bounds__(128, 10)
void glcm_martingale_kernel(const float* __restrict__ x, float* __restrict__ out)
{
    __shared__ __align__(16) float2 sm[SW * SW];   // (p, p*log(p+eps)), zero-padded halo

    const int bc    = blockIdx.z;                  // plane (b*C + c)
    const int tileX = blockIdx.x * 32;
    const int tileY = blockIdx.y * 32;
    const float* __restrict__ xin = x + (size_t)bc * 65536;

    const int tid  = threadIdx.y * 16 + threadIdx.x;

    // ---- load 34x34 halo tile; compute plog once per element ----
    {
        const int lane = tid & 31;
        const int rr0  = tid >> 5;                 // 0..3
        #pragma unroll
        for (int r = rr0; r < SW; r += 4) {
            int gh = tileY - 1 + r;
            bool rok = (unsigned)gh < 256u;
            const float* __restrict__ rp = xin + gh * 256 + (tileX - 1);
            #pragma unroll
            for (int j = 0; j < 2; j++) {
                int c = lane + j * 32;
                if (c < SW) {
                    int gw = tileX - 1 + c;
                    float v = (rok && (unsigned)gw < 256u) ? rp[c] : 0.0f;
                    sm[r * SW + c] = make_float2(v, v * __logf(v + EPSF));
                }
            }
        }
    }
    __syncthreads();

    const int j0 = 2 * threadIdx.x;   // leftmost tap col; outputs cols j0, j0+1
    const int r0 = threadIdx.y * 4;   // first output row in tile

    float pa0, pb0, pc0, pd0, pa1, pb1, pc1, pd1, pa2, pb2, pc2, pd2;
    float rsL0, rsR0, rqL0, rqR0, rlL0, rlR0;
    float rsL1, rsR1, rqL1, rqR1, rlL1, rlR1;
    float rsL2, rsR2, rqL2, rqR2, rlL2, rlR2;

    LOADROW(r0,     pa0, pb0, pc0, pd0, rsL0, rsR0, rqL0, rqR0, rlL0, rlR0);
    LOADROW(r0 + 1, pa1, pb1, pc1, pd1, rsL1, rsR1, rqL1, rqR1, rlL1, rlR1);

    const size_t plane = 65536;
    float* obase = out + (size_t)bc * 4 * plane
                       + (size_t)(tileY + r0) * 256 + (tileX + j0);

    #pragma unroll
    for (int k = 0; k < 4; k++) {
        LOADROW(r0 + k + 2, pa2, pb2, pc2, pd2, rsL2, rsR2, rqL2, rqR2, rlL2, rlR2);

        float S1L = rsL0 + rsL1 + rsL2;
        float S2L = rqL0 + rqL1 + rqL2;
        float SLL = rlL0 + rlL1 + rlL2;
        float S1R = rsR0 + rsR1 + rsR2;
        float S2R = rqR0 + rqR1 + rqR2;
        float SLR = rlR0 + rlR1 + rlR2;

        float4 fL = feat(S1L, S2L, SLL, pa0, pb0, pc0, pa1, pb1, pc1, pa2, pb2, pc2);
        float4 fR = feat(S1R, S2R, SLR, pb0, pc0, pd0, pb1, pc1, pd1, pb2, pc2, pd2);

        float* o = obase + (size_t)k * 256;
        *(float2*)&o[0]         = make_float2(fmaf(fL.x, EXPN, EPSC), fmaf(fR.x, EXPN, EPSC));
        *(float2*)&o[plane]     = make_float2(fmaf(fL.y, EXPN, EPSC), fmaf(fR.y, EXPN, EPSC));
        *(float2*)&o[2 * plane] = make_float2(fmaf(fL.z, EXPN, EPSC), fmaf(fR.z, EXPN, EPSC));
        *(float2*)&o[3 * plane] = make_float2(fmaf(fL.w, EXPN, EPSC), fmaf(fR.w, EXPN, EPSC));

        // roll window down one row (register renames under full unroll)
        pa0 = pa1; pb0 = pb1; pc0 = pc1; pd0 = pd1;
        pa1 = pa2; pb1 = pb2; pc1 = pc2; pd1 = pd2;
        rsL0 = rsL1; rsR0 = rsR1; rqL0 = rqL1; rqR0 = rqR1; rlL0 = rlL1; rlR0 = rlR1;
        rsL1 = rsL2; rsR1 = rsR2; rqL1 = rqL2; rqR1 = rqR2; rlL1 = rlL2; rlR1 = rlR2;
    }
}

extern "C" void kernel_launch(void* const* d_in, const int* in_sizes, int n_in,
                              void* d_out, int out_size)
{
    const float* x = (const float*)d_in[0];
    float* out     = (float*)d_out;

    dim3 block(16, 8, 1);                 // 128 threads; thread = 2 cols x 4 rows
    dim3 grid(256 / 32, 256 / 32, 128);   // 8 x 8 x 128 = 8192 blocks
    glcm_martingale_kernel<<<grid, block>>>(x, out);
}

// round 9
// speedup vs baseline: 1.0613x; 1.0613x over previous
#include <cuda_runtime.h>
#include <cuda_bf16.h>

// TextureMartingaleModule: per-channel 3x3 GLCM features, zero padding.
// x: [8,16,256,256] f32 -> out: [8,64,256,256] f32
//   contrast    = mean(((p-mean)/std)^2),  std = sqrt(sd/8)+eps
//   energy      = mean(p^2)
//   entropy     = -mean(p*log(p+eps))
//   homogeneity = 1 / mean(1 + |p-mean|)
// M = (f + eps)*e^{-0.5}  (theta=1)
//
// Validated identities (rel_err ~1.5e-7 in prior rounds):
//   sd = S2 - S1*mean
//   contrast = (8/9)*(1 - 2*eps*rsqrt(sd/8)), bit-trick rsqrt (no MUFU)
//
// Structure = R3 (the only 60%-issue config): 1 px/thread, 32x8 block,
// lane-contiguous smem access. New: smem holds interleaved float2
// (p, p*log(p+eps)) -> 3 LDS.64/row-step, lane stride 8B = conflict-free.

#define EPSF 1e-6f
#define EXPN 0.60653065971263342f      /* e^-0.5 */
#define EPSC (EPSF * EXPN)
#define KE   (EXPN / 9.0f)             /* e^-0.5 / 9 */
#define KC   (8.0f / 9.0f * EXPN)
#define SW 34

__global__ __launch_bounds__(256, 6)
void glcm_martingale_kernel(const float* __restrict__ x, float* __restrict__ out)
{
    __shared__ __align__(16) float2 sm[SW * SW];   // (p, p*log(p+eps)), zero-padded halo

    const int bc    = blockIdx.z;
    const int tileX = blockIdx.x * 32;
    const int tileY = blockIdx.y * 32;
    const float* __restrict__ xin = x + (size_t)bc * 65536;

    const int tx = threadIdx.x;       // 0..31
    const int ty = threadIdx.y;       // 0..7 (warp id)

    // ---- load 34x34 halo; plog computed once per element ----
    #pragma unroll
    for (int j = 0; j < 5; j++) {
        int r = ty + 8 * j;
        if (r < SW) {
            int gh = tileY - 1 + r;
            bool rok = (unsigned)gh < 256u;
            const float* __restrict__ rp = xin + gh * 256 + (tileX - 1);
            int gw = tileX - 1 + tx;
            float v = (rok && (unsigned)gw < 256u) ? rp[tx] : 0.0f;
            sm[r * SW + tx] = make_float2(v, v * __logf(v + EPSF));
            if (tx < 2) {
                int c2 = tx + 32;
                int gw2 = tileX - 1 + c2;
                float v2 = (rok && (unsigned)gw2 < 256u) ? rp[c2] : 0.0f;
                sm[r * SW + c2] = make_float2(v2, v2 * __logf(v2 + EPSF));
            }
        }
    }
    __syncthreads();

    const int r0 = ty * 4;            // first output row in tile

    // rolling 3x3 p-window + rolling per-row sums (p, p^2, plog)
    float pa0, pb0, pc0, pa1, pb1, pc1, pa2, pb2, pc2;
    float rs0, rq0, rl0, rs1, rq1, rl1, rs2, rq2, rl2;

    {
        const float2* row = sm + r0 * SW + tx;
        float2 u0 = row[0], u1 = row[1], u2 = row[2];
        pa0 = u0.x; pb0 = u1.x; pc0 = u2.x;
        rs0 = pa0 + pb0 + pc0;
        rq0 = fmaf(pa0, pa0, fmaf(pb0, pb0, pc0 * pc0));
        rl0 = u0.y + u1.y + u2.y;
    }
    {
        const float2* row = sm + (r0 + 1) * SW + tx;
        float2 u0 = row[0], u1 = row[1], u2 = row[2];
        pa1 = u0.x; pb1 = u1.x; pc1 = u2.x;
        rs1 = pa1 + pb1 + pc1;
        rq1 = fmaf(pa1, pa1, fmaf(pb1, pb1, pc1 * pc1));
        rl1 = u0.y + u1.y + u2.y;
    }

    const size_t plane = 65536;
    float* obase = out + (size_t)bc * 4 * plane
                       + (size_t)(tileY + r0) * 256 + (tileX + tx);

    #pragma unroll
    for (int k = 0; k < 4; k++) {
        {
            const float2* row = sm + (r0 + k + 2) * SW + tx;
            float2 u0 = row[0], u1 = row[1], u2 = row[2];
            pa2 = u0.x; pb2 = u1.x; pc2 = u2.x;
            rs2 = pa2 + pb2 + pc2;
            rq2 = fmaf(pa2, pa2, fmaf(pb2, pb2, pc2 * pc2));
            rl2 = u0.y + u1.y + u2.y;
        }

        float S1 = rs0 + rs1 + rs2;
        float S2 = rq0 + rq1 + rq2;
        float SL = rl0 + rl1 + rl2;

        const float inv9 = 1.0f / 9.0f;
        float mean = S1 * inv9;
        float sd = fmaxf(fmaf(-S1, mean, S2), 1e-12f);   // sum (p-mean)^2

        // contrast (folded): (8/9)(1 - 2eps*r) * e^-0.5 + eps*e^-0.5
        float r  = __int_as_float(0x5f3759df - (__float_as_int(sd * 0.125f) >> 1));
        float cf = fmaxf(fmaf(-2.0f * EPSF, r, 1.0f), 0.0f);

        // homogeneity: sum |p - mean|
        float a = fabsf(pa0 - mean);
        a += fabsf(pb0 - mean); a += fabsf(pc0 - mean);
        a += fabsf(pa1 - mean); a += fabsf(pb1 - mean); a += fabsf(pc1 - mean);
        a += fabsf(pa2 - mean); a += fabsf(pb2 - mean); a += fabsf(pc2 - mean);
        float h = __fdividef(1.0f, fmaf(a, inv9, 1.0f));

        float* o = obase + (size_t)k * 256;
        o[0]         = fmaf(cf, KC,   EPSC);   // contrast
        o[plane]     = fmaf(S2, KE,   EPSC);   // energy
        o[2 * plane] = fmaf(SL, -KE,  EPSC);   // entropy
        o[3 * plane] = fmaf(h,  EXPN, EPSC);   // homogeneity

        // roll window (renamed away by full unroll)
        pa0 = pa1; pb0 = pb1; pc0 = pc1;
        pa1 = pa2; pb1 = pb2; pc1 = pc2;
        rs0 = rs1; rq0 = rq1; rl0 = rl1;
        rs1 = rs2; rq1 = rq2; rl1 = rl2;
    }
}

extern "C" void kernel_launch(void* const* d_in, const int* in_sizes, int n_in,
                              void* d_out, int out_size)
{
    const float* x = (const float*)d_in[0];
    float* out     = (float*)d_out;

    dim3 block(32, 8, 1);                 // 256 threads, 1 px/thread, 4 rows each
    dim3 grid(256 / 32, 256 / 32, 128);   // 8 x 8 x 128 = 8192 blocks
    glcm_martingale_kernel<<<grid, block>>>(x, out);
}

// round 10
// speedup vs baseline: 1.1614x; 1.0944x over previous
#include <cuda_runtime.h>
#include <cuda_bf16.h>

// TextureMartingaleModule: per-channel 3x3 GLCM features, zero padding.
// x: [8,16,256,256] f32 -> out: [8,64,256,256] f32
//   contrast    = mean(((p-mean)/std)^2),  std = sqrt(sd/8)+eps
//   energy      = mean(p^2)
//   entropy     = -mean(p*log(p+eps))
//   homogeneity = 1 / mean(1 + |p-mean|)
// M = (f+eps)*e^{-0.5}  (theta=1)
//
// Validated identities (rel_err ~1.5e-7):
//   sd = S2 - S1*mean ; contrast = (8/9)*(1 - 2*eps*rsqrt(sd/8)) w/ bit-trick rsqrt
//
// This round: R3's layout (separate sp/sl float arrays, 1 px/thread,
// lane-contiguous LDS.32) but ALL 36 window loads batched upfront into
// registers (MLP ~36), then 4 pure-ALU feature blocks with tree-structured
// |dev| sums. Latency-structure fix, not instruction-count fix.

#define EPSF 1e-6f
#define EXPN 0.60653065971263342f      /* e^-0.5 */
#define EPSC (EPSF * EXPN)
#define KE   (EXPN / 9.0f)
#define KC   (8.0f / 9.0f * EXPN)
#define SROW 34

__global__ __launch_bounds__(256, 4)
void glcm_martingale_kernel(const float* __restrict__ x, float* __restrict__ out)
{
    __shared__ float sp[SROW * SROW];   // raw values, zero-padded halo
    __shared__ float sl[SROW * SROW];   // p * log(p + eps)

    const int bc    = blockIdx.z;
    const int tileX = blockIdx.x * 32;
    const int tileY = blockIdx.y * 32;
    const float* __restrict__ xin = x + (size_t)bc * 65536;

    const int tx  = threadIdx.x;        // 0..31
    const int ty  = threadIdx.y;        // 0..7
    const int tid = ty * 32 + tx;

    // ---- load 34x34 halo tile; plog computed once per element (R3-proven) ----
    #pragma unroll
    for (int i = tid; i < SROW * SROW; i += 256) {
        int r  = i / SROW;
        int cc = i - r * SROW;
        int gh = tileY - 1 + r;
        int gw = tileX - 1 + cc;
        float v = 0.0f;
        if ((unsigned)gh < 256u && (unsigned)gw < 256u)
            v = xin[gh * 256 + gw];
        sp[i] = v;
        sl[i] = v * __logf(v + EPSF);
    }
    __syncthreads();

    const int r0 = ty * 4;              // first output row in tile (rows r0..r0+5 used)

    const size_t plane = 65536;
    float* obase = out + (size_t)bc * 4 * plane
                       + (size_t)(tileY + r0) * 256 + (tileX + tx);

    // ---- batch-load all 6 smem rows into registers (36 LDS, high MLP) ----
    float pA[6], pB[6], pC[6];          // taps per row
    float rs[6], rq[6], rl[6];          // per-row sums of p, p^2, plog
    #pragma unroll
    for (int j = 0; j < 6; j++) {
        const float* rowp = sp + (r0 + j) * SROW + tx;
        float a = rowp[0], b = rowp[1], c = rowp[2];
        const float* rowl = sl + (r0 + j) * SROW + tx;
        float la = rowl[0], lb = rowl[1], lc = rowl[2];
        pA[j] = a; pB[j] = b; pC[j] = c;
        rs[j] = a + b + c;
        rq[j] = fmaf(a, a, fmaf(b, b, c * c));
        rl[j] = la + lb + lc;
    }

    // ---- 4 pure-ALU feature blocks ----
    #pragma unroll
    for (int k = 0; k < 4; k++) {
        float S1 = rs[k] + rs[k + 1] + rs[k + 2];
        float S2 = rq[k] + rq[k + 1] + rq[k + 2];
        float SL = rl[k] + rl[k + 1] + rl[k + 2];

        const float inv9 = 1.0f / 9.0f;
        float mean = S1 * inv9;
        float sd = fmaxf(fmaf(-S1, mean, S2), 1e-12f);   // sum (p-mean)^2

        // contrast = (8/9)*(1 - 2*eps*rsqrt(sd/8)); bit-trick rsqrt (no MUFU)
        float r  = __int_as_float(0x5f3759df - (__float_as_int(sd * 0.125f) >> 1));
        float cf = fmaxf(fmaf(-2.0f * EPSF, r, 1.0f), 0.0f);

        // homogeneity: tree-structured sum |p - mean| (short critical path)
        float d0 = fabsf(pA[k]     - mean);
        float d1 = fabsf(pB[k]     - mean);
        float d2 = fabsf(pC[k]     - mean);
        float d3 = fabsf(pA[k + 1] - mean);
        float d4 = fabsf(pB[k + 1] - mean);
        float d5 = fabsf(pC[k + 1] - mean);
        float d6 = fabsf(pA[k + 2] - mean);
        float d7 = fabsf(pB[k + 2] - mean);
        float d8 = fabsf(pC[k + 2] - mean);
        float s01 = d0 + d1, s23 = d2 + d3, s45 = d4 + d5, s67 = d6 + d7;
        float a = ((s01 + s23) + (s45 + s67)) + d8;
        float h = __fdividef(1.0f, fmaf(a, inv9, 1.0f));

        float* o = obase + (size_t)k * 256;
        o[0]         = fmaf(cf, KC,   EPSC);   // contrast
        o[plane]     = fmaf(S2, KE,   EPSC);   // energy
        o[2 * plane] = fmaf(SL, -KE,  EPSC);   // entropy
        o[3 * plane] = fmaf(h,  EXPN, EPSC);   // homogeneity
    }
}

extern "C" void kernel_launch(void* const* d_in, const int* in_sizes, int n_in,
                              void* d_out, int out_size)
{
    const float* x = (const float*)d_in[0];
    float* out     = (float*)d_out;

    dim3 block(32, 8, 1);                 // 256 threads, 1 px/thread, 4 rows each
    dim3 grid(256 / 32, 256 / 32, 128);   // 8 x 8 x 128 = 8192 blocks
    glcm_martingale_kernel<<<grid, block>>>(x, out);
}

// round 11
// speedup vs baseline: 1.2063x; 1.0387x over previous
#include <cuda_runtime.h>
#include <cuda_bf16.h>

// TextureMartingaleModule: per-channel 3x3 GLCM features, zero padding.
// x: [8,16,256,256] f32 -> out: [8,64,256,256] f32
//   contrast    = mean(((p-mean)/std)^2),  std = sqrt(sd/8)+eps
//   energy      = mean(p^2)
//   entropy     = -mean(p*log(p+eps))
//   homogeneity = 1 / mean(1 + |p-mean|)
// M = (f+eps)*e^{-0.5}  (theta=1)
//
// Validated identities (rel_err ~1.5e-7):
//   sd = S2 - S1*mean ; contrast = (8/9)*(1 - 2*eps*rsqrt(sd/8)) w/ bit-trick rsqrt
//
// This round: R3's layout (separate sp/sl float arrays, 1 px/thread,
// lane-contiguous LDS.32) but ALL 36 window loads batched upfront into
// registers (MLP ~36), then 4 pure-ALU feature blocks with tree-structured
// |dev| sums. Latency-structure fix, not instruction-count fix.

#define EPSF 1e-6f
#define EXPN 0.60653065971263342f      /* e^-0.5 */
#define EPSC (EPSF * EXPN)
#define KE   (EXPN / 9.0f)
#define KC   (8.0f / 9.0f * EXPN)
#define SROW 34

__global__ __launch_bounds__(256, 4)
void glcm_martingale_kernel(const float* __restrict__ x, float* __restrict__ out)
{
    __shared__ float sp[SROW * SROW];   // raw values, zero-padded halo
    __shared__ float sl[SROW * SROW];   // p * log(p + eps)

    const int bc    = blockIdx.z;
    const int tileX = blockIdx.x * 32;
    const int tileY = blockIdx.y * 32;
    const float* __restrict__ xin = x + (size_t)bc * 65536;

    const int tx  = threadIdx.x;        // 0..31
    const int ty  = threadIdx.y;        // 0..7
    const int tid = ty * 32 + tx;

    // ---- load 34x34 halo tile; plog computed once per element (R3-proven) ----
    #pragma unroll
    for (int i = tid; i < SROW * SROW; i += 256) {
        int r  = i / SROW;
        int cc = i - r * SROW;
        int gh = tileY - 1 + r;
        int gw = tileX - 1 + cc;
        float v = 0.0f;
        if ((unsigned)gh < 256u && (unsigned)gw < 256u)
            v = xin[gh * 256 + gw];
        sp[i] = v;
        sl[i] = v * __logf(v + EPSF);
    }
    __syncthreads();

    const int r0 = ty * 4;              // first output row in tile (rows r0..r0+5 used)

    const size_t plane = 65536;
    float* obase = out + (size_t)bc * 4 * plane
                       + (size_t)(tileY + r0) * 256 + (tileX + tx);

    // ---- batch-load all 6 smem rows into registers (36 LDS, high MLP) ----
    float pA[6], pB[6], pC[6];          // taps per row
    float rs[6], rq[6], rl[6];          // per-row sums of p, p^2, plog
    #pragma unroll
    for (int j = 0; j < 6; j++) {
        const float* rowp = sp + (r0 + j) * SROW + tx;
        float a = rowp[0], b = rowp[1], c = rowp[2];
        const float* rowl = sl + (r0 + j) * SROW + tx;
        float la = rowl[0], lb = rowl[1], lc = rowl[2];
        pA[j] = a; pB[j] = b; pC[j] = c;
        rs[j] = a + b + c;
        rq[j] = fmaf(a, a, fmaf(b, b, c * c));
        rl[j] = la + lb + lc;
    }

    // ---- 4 pure-ALU feature blocks ----
    #pragma unroll
    for (int k = 0; k < 4; k++) {
        float S1 = rs[k] + rs[k + 1] + rs[k + 2];
        float S2 = rq[k] + rq[k + 1] + rq[k + 2];
        float SL = rl[k] + rl[k + 1] + rl[k + 2];

        const float inv9 = 1.0f / 9.0f;
        float mean = S1 * inv9;
        float sd = fmaxf(fmaf(-S1, mean, S2), 1e-12f);   // sum (p-mean)^2

        // contrast = (8/9)*(1 - 2*eps*rsqrt(sd/8)); bit-trick rsqrt (no MUFU)
        float r  = __int_as_float(0x5f3759df - (__float_as_int(sd * 0.125f) >> 1));
        float cf = fmaxf(fmaf(-2.0f * EPSF, r, 1.0f), 0.0f);

        // homogeneity: tree-structured sum |p - mean| (short critical path)
        float d0 = fabsf(pA[k]     - mean);
        float d1 = fabsf(pB[k]     - mean);
        float d2 = fabsf(pC[k]     - mean);
        float d3 = fabsf(pA[k + 1] - mean);
        float d4 = fabsf(pB[k + 1] - mean);
        float d5 = fabsf(pC[k + 1] - mean);
        float d6 = fabsf(pA[k + 2] - mean);
        float d7 = fabsf(pB[k + 2] - mean);
        float d8 = fabsf(pC[k + 2] - mean);
        float s01 = d0 + d1, s23 = d2 + d3, s45 = d4 + d5, s67 = d6 + d7;
        float a = ((s01 + s23) + (s45 + s67)) + d8;
        float h = __fdividef(1.0f, fmaf(a, inv9, 1.0f));

        float* o = obase + (size_t)k * 256;
        o[0]         = fmaf(cf, KC,   EPSC);   // contrast
        o[plane]     = fmaf(S2, KE,   EPSC);   // energy
        o[2 * plane] = fmaf(SL, -KE,  EPSC);   // entropy
        o[3 * plane] = fmaf(h,  EXPN, EPSC);   // homogeneity
    }
}

extern "C" void kernel_launch(void* const* d_in, const int* in_sizes, int n_in,
                              void* d_out, int out_size)
{
    const float* x = (const float*)d_in[0];
    float* out     = (float*)d_out;

    dim3 block(32, 8, 1);                 // 256 threads, 1 px/thread, 4 rows each
    dim3 grid(256 / 32, 256 / 32, 128);   // 8 x 8 x 128 = 8192 blocks
    glcm_martingale_kernel<<<grid, block>>>(x, out);
}